// round 5
// baseline (speedup 1.0000x reference)
#include <cuda_runtime.h>
#include <cstdint>
#include <cstddef>

#define NHID 1024
#define NHEAD 16
#define DK   64
#define BB   2
#define SS   2048
#define QKVC 3072              // NHEAD * (2*64 + 64)
#define ROWS (BB*SS)           // 4096
#define PAD  68                // smem row stride (floats), 16B-aligned, depads banks

#define NEG_INF (__int_as_float(0xff800000))

// Scratch (allocation-free rule: device globals)
__device__ float g_qkv[(size_t)ROWS * QKVC];   // [row, h*192 + {q:0..63, k:64..127, v:128..191}]
__device__ float g_ctx[(size_t)ROWS * NHID];   // [row, h*64 + d]
__device__ int   g_mask_mode;                  // 0=int32, 1=uint8, 2=float32

// ---------------------------------------------------------------------------
// Probe the mask buffer's dtype from its bit patterns (first 16KB).
//   int32 bool:  every 32-bit word is 0 or 1
//   uint8 bool:  every byte is 0 or 1 (some word > 1)
//   float32:     words are 0x00000000 or 0x3F800000
// ---------------------------------------------------------------------------
__global__ void probe_mask_kernel(const uint4* __restrict__ m) {
    __shared__ int s_flags;
    if (threadIdx.x == 0) s_flags = 0;
    __syncthreads();
    uint4 v = m[threadIdx.x];
    unsigned int ws[4] = {v.x, v.y, v.z, v.w};
    int f = 0;
    #pragma unroll
    for (int i = 0; i < 4; i++) {
        unsigned int w = ws[i];
        if (w > 1u)                          f |= 1;  // not int32 0/1
        if ((w & 0xFEFEFEFEu) != 0u)         f |= 2;  // some byte > 1
        if (w != 0u && w != 0x3F800000u)     f |= 4;  // not float 0/1.0
    }
    if (f) atomicOr(&s_flags, f);
    __syncthreads();
    if (threadIdx.x == 0) {
        int fl = s_flags, mode;
        if      (!(fl & 1)) mode = 0;   // int32
        else if (!(fl & 2)) mode = 1;   // uint8
        else if (!(fl & 4)) mode = 2;   // float32
        else                mode = 1;   // fallback
        g_mask_mode = mode;
    }
}

// ---------------------------------------------------------------------------
// 128x128x16 fp32 SIMT GEMM: C = A@B + bias (+ resid). M,N%128==0, K%16==0.
// ---------------------------------------------------------------------------
__global__ __launch_bounds__(256) void gemm_kernel(
    const float* __restrict__ A, const float* __restrict__ Bm,
    const float* __restrict__ bias, const float* __restrict__ resid,
    float* __restrict__ C, int M, int N, int K)
{
    __shared__ float As[16][132];   // A transposed: As[k][m]
    __shared__ float Bs[16][128];   // Bs[k][n]

    const int tid = threadIdx.x;
    const int tx = tid & 15, ty = tid >> 4;
    const int row0 = blockIdx.y * 128, col0 = blockIdx.x * 128;

    float acc[8][8] = {};

    for (int kt = 0; kt < K; kt += 16) {
        #pragma unroll
        for (int r = 0; r < 2; r++) {
            int f = tid * 2 + r;                 // 0..511
            int arow = f >> 2, acol = (f & 3) * 4;
            float4 av = *(const float4*)&A[(size_t)(row0 + arow) * K + kt + acol];
            As[acol + 0][arow] = av.x; As[acol + 1][arow] = av.y;
            As[acol + 2][arow] = av.z; As[acol + 3][arow] = av.w;
        }
        #pragma unroll
        for (int r = 0; r < 2; r++) {
            int f = tid * 2 + r;
            int brow = f >> 5, bcol = (f & 31) * 4;
            *(float4*)&Bs[brow][bcol] =
                *(const float4*)&Bm[(size_t)(kt + brow) * N + col0 + bcol];
        }
        __syncthreads();

        #pragma unroll
        for (int kk = 0; kk < 16; kk++) {
            float4 a0 = *(float4*)&As[kk][ty * 4];
            float4 a1 = *(float4*)&As[kk][64 + ty * 4];
            float4 b0 = *(float4*)&Bs[kk][tx * 4];
            float4 b1 = *(float4*)&Bs[kk][64 + tx * 4];
            float av[8] = {a0.x, a0.y, a0.z, a0.w, a1.x, a1.y, a1.z, a1.w};
            float bv[8] = {b0.x, b0.y, b0.z, b0.w, b1.x, b1.y, b1.z, b1.w};
            #pragma unroll
            for (int i = 0; i < 8; i++)
                #pragma unroll
                for (int j = 0; j < 8; j++)
                    acc[i][j] = fmaf(av[i], bv[j], acc[i][j]);
        }
        __syncthreads();
    }

    #pragma unroll
    for (int i = 0; i < 8; i++) {
        int r = row0 + ((i < 4) ? (ty * 4 + i) : (64 + ty * 4 + (i - 4)));
        #pragma unroll
        for (int jh = 0; jh < 2; jh++) {
            int c = col0 + (jh ? (64 + tx * 4) : (tx * 4));
            float4 o;
            o.x = acc[i][jh * 4 + 0] + bias[c + 0];
            o.y = acc[i][jh * 4 + 1] + bias[c + 1];
            o.z = acc[i][jh * 4 + 2] + bias[c + 2];
            o.w = acc[i][jh * 4 + 3] + bias[c + 3];
            if (resid) {
                float4 rv = *(const float4*)&resid[(size_t)r * N + c];
                o.x += rv.x; o.y += rv.y; o.z += rv.z; o.w += rv.w;
            }
            *(float4*)&C[(size_t)r * N + c] = o;
        }
    }
}

// ---------------------------------------------------------------------------
// Flash-style attention: one CTA = 64 q-rows of one (b,h). Online softmax.
// ---------------------------------------------------------------------------
__global__ __launch_bounds__(256) void attn_kernel(
    const void* __restrict__ mask, float* __restrict__ ctx)
{
    extern __shared__ float sm[];
    float* qs = sm;
    float* ks = qs + 64 * PAD;
    float* vs = ks + 64 * PAD;
    float* ss = vs + 64 * PAD;
    float* rowm = ss + 64 * PAD;
    float* rowl = rowm + 64;
    float* rowa = rowl + 64;

    const int tid = threadIdx.x;
    const int tx = tid & 15, ty = tid >> 4;
    const int q0 = blockIdx.x * 64;
    const int h  = blockIdx.y;
    const int b  = blockIdx.z;
    const int i0 = ty * 4, j0 = tx * 4;
    const int mmode = g_mask_mode;

    // Load Q tile (64x64), 4 float4 per thread
    #pragma unroll
    for (int i = 0; i < 4; i++) {
        int f = tid + i * 256;
        int row = f >> 4, d4 = (f & 15) * 4;
        *(float4*)&qs[row * PAD + d4] =
            *(const float4*)&g_qkv[(size_t)(b * SS + q0 + row) * QKVC + h * 192 + d4];
    }
    if (tid < 64) { rowm[tid] = NEG_INF; rowl[tid] = 0.f; }

    float o[4][4] = {};

    for (int kt = 0; kt < SS; kt += 64) {
        __syncthreads();   // previous tile's ss/ks/vs reads done; also covers q-load/init
        // Load K,V tiles
        #pragma unroll
        for (int i = 0; i < 4; i++) {
            int f = tid + i * 256;
            int row = f >> 4, d4 = (f & 15) * 4;
            size_t base = (size_t)(b * SS + kt + row) * QKVC + h * 192;
            *(float4*)&ks[row * PAD + d4] = *(const float4*)&g_qkv[base + 64 + d4];
            *(float4*)&vs[row * PAD + d4] = *(const float4*)&g_qkv[base + 128 + d4];
        }
        __syncthreads();

        // S = Q @ K^T (4x4 micro-tile per thread)
        float s4[4][4] = {};
        #pragma unroll
        for (int d = 0; d < 64; d += 4) {
            float4 qf[4], kf[4];
            #pragma unroll
            for (int i = 0; i < 4; i++) qf[i] = *(float4*)&qs[(i0 + i) * PAD + d];
            #pragma unroll
            for (int j = 0; j < 4; j++) kf[j] = *(float4*)&ks[(j0 + j) * PAD + d];
            #pragma unroll
            for (int i = 0; i < 4; i++)
                #pragma unroll
                for (int j = 0; j < 4; j++)
                    s4[i][j] += qf[i].x * kf[j].x + qf[i].y * kf[j].y
                              + qf[i].z * kf[j].z + qf[i].w * kf[j].w;
        }
        // scale + mask -> ss  (mask layout: [b, q, h, k], dtype per g_mask_mode)
        #pragma unroll
        for (int i = 0; i < 4; i++) {
            size_t midx = ((size_t)(b * SS + q0 + i0 + i) * NHEAD + h) * SS + kt + j0;
            bool mk[4];
            if (mmode == 0) {
                int4 t = *(const int4*)((const int*)mask + midx);
                mk[0] = t.x != 0; mk[1] = t.y != 0; mk[2] = t.z != 0; mk[3] = t.w != 0;
            } else if (mmode == 1) {
                uchar4 t = *(const uchar4*)((const unsigned char*)mask + midx);
                mk[0] = t.x != 0; mk[1] = t.y != 0; mk[2] = t.z != 0; mk[3] = t.w != 0;
            } else {
                float4 t = *(const float4*)((const float*)mask + midx);
                mk[0] = t.x != 0.f; mk[1] = t.y != 0.f; mk[2] = t.z != 0.f; mk[3] = t.w != 0.f;
            }
            #pragma unroll
            for (int j = 0; j < 4; j++)
                ss[(i0 + i) * PAD + j0 + j] = mk[j] ? s4[i][j] * 0.125f : NEG_INF;
        }
        __syncthreads();

        // Online softmax: 4 threads per row
        {
            int row = tid >> 2, l4 = tid & 3;
            float mloc = NEG_INF;
            #pragma unroll
            for (int c = 0; c < 16; c++)
                mloc = fmaxf(mloc, ss[row * PAD + l4 * 16 + c]);
            mloc = fmaxf(mloc, __shfl_xor_sync(0xffffffffu, mloc, 1));
            mloc = fmaxf(mloc, __shfl_xor_sync(0xffffffffu, mloc, 2));
            float mold = rowm[row];
            float mnew = fmaxf(mold, mloc);
            float sum = 0.f;
            #pragma unroll
            for (int c = 0; c < 16; c++) {
                float s = ss[row * PAD + l4 * 16 + c];
                float p = (s == NEG_INF) ? 0.f : __expf(s - mnew);
                ss[row * PAD + l4 * 16 + c] = p;
                sum += p;
            }
            sum += __shfl_xor_sync(0xffffffffu, sum, 1);
            sum += __shfl_xor_sync(0xffffffffu, sum, 2);
            if (l4 == 0) {
                float alpha = (mnew == NEG_INF) ? 1.f : __expf(mold - mnew);
                rowl[row] = rowl[row] * alpha + sum;
                rowm[row] = mnew;
                rowa[row] = alpha;
            }
        }
        __syncthreads();

        // O = O*alpha + P @ V
        #pragma unroll
        for (int i = 0; i < 4; i++) {
            float a = rowa[i0 + i];
            #pragma unroll
            for (int j = 0; j < 4; j++) o[i][j] *= a;
        }
        #pragma unroll
        for (int k = 0; k < 64; k += 4) {
            float4 pf[4];
            #pragma unroll
            for (int i = 0; i < 4; i++) pf[i] = *(float4*)&ss[(i0 + i) * PAD + k];
            #pragma unroll
            for (int kk = 0; kk < 4; kk++) {
                float4 vf = *(float4*)&vs[(k + kk) * PAD + j0];
                #pragma unroll
                for (int i = 0; i < 4; i++) {
                    float p = (kk == 0) ? pf[i].x : (kk == 1) ? pf[i].y
                            : (kk == 2) ? pf[i].z : pf[i].w;
                    o[i][0] = fmaf(p, vf.x, o[i][0]);
                    o[i][1] = fmaf(p, vf.y, o[i][1]);
                    o[i][2] = fmaf(p, vf.z, o[i][2]);
                    o[i][3] = fmaf(p, vf.w, o[i][3]);
                }
            }
        }
    }

    // Normalize + write ctx[(b*SS+q), h*64+d]
    #pragma unroll
    for (int i = 0; i < 4; i++) {
        float l = rowl[i0 + i];
        float linv = (l > 0.f) ? (1.f / l) : 0.f;
        float4 ov = make_float4(o[i][0] * linv, o[i][1] * linv,
                                o[i][2] * linv, o[i][3] * linv);
        *(float4*)&ctx[(size_t)(b * SS + q0 + i0 + i) * NHID + h * 64 + j0] = ov;
    }
}

// ---------------------------------------------------------------------------
extern "C" void kernel_launch(void* const* d_in, const int* in_sizes, int n_in,
                              void* d_out, int out_size)
{
    const float* x     = (const float*)d_in[0];
    const void*  mask  = d_in[1];
    const float* W_qkv = (const float*)d_in[2];
    const float* b_qkv = (const float*)d_in[3];
    const float* W_out = (const float*)d_in[4];
    const float* b_out = (const float*)d_in[5];
    float*       out   = (float*)d_out;

    float *qkv_ptr, *ctx_ptr;
    cudaGetSymbolAddress((void**)&qkv_ptr, g_qkv);
    cudaGetSymbolAddress((void**)&ctx_ptr, g_ctx);

    const int smem_attn = (4 * 64 * PAD + 3 * 64) * (int)sizeof(float); // 70400 B
    cudaFuncSetAttribute(attn_kernel,
                         cudaFuncAttributeMaxDynamicSharedMemorySize, smem_attn);

    // 0) Probe mask dtype (writes g_mask_mode)
    probe_mask_kernel<<<1, 1024>>>((const uint4*)mask);

    // 1) QKV projection: [4096,1024] @ [1024,3072] + b
    dim3 g1(QKVC / 128, ROWS / 128);
    gemm_kernel<<<g1, 256>>>(x, W_qkv, b_qkv, nullptr, qkv_ptr, ROWS, QKVC, NHID);

    // 2) Masked flash attention
    dim3 ga(SS / 64, NHEAD, BB);
    attn_kernel<<<ga, 256, smem_attn>>>(mask, ctx_ptr);

    // 3) Output projection + residual: [4096,1024] @ [1024,1024] + b + x
    dim3 g3(NHID / 128, ROWS / 128);
    gemm_kernel<<<g3, 256>>>(ctx_ptr, W_out, b_out, x, out, ROWS, NHID, NHID);
}

// round 8
// speedup vs baseline: 5.6427x; 5.6427x over previous
#include <cuda_runtime.h>
#include <cuda_bf16.h>
#include <cstdint>
#include <cstddef>

#define NHID 1024
#define NHEAD 16
#define BB   2
#define SS   2048
#define QKVC 3072              // NHEAD * (2*64 + 64)
#define ROWS (BB*SS)           // 4096

#define NEG_INF (__int_as_float(0xff800000))

// Scratch (allocation-free rule: device globals)
__device__ __nv_bfloat16 g_qkvh[(size_t)ROWS * QKVC];   // [row][h*192 + {q,k,v}]
__device__ __nv_bfloat16 g_ctxh[(size_t)ROWS * NHID];   // [row][h*64 + d]
__device__ __nv_bfloat16 g_wqkvt[(size_t)QKVC * NHID];  // W_qkv^T  [n][k] bf16
__device__ __nv_bfloat16 g_woutt[(size_t)NHID * NHID];  // W_out^T  [n][k] bf16
__device__ int g_mask_mode;                             // 0=int32, 1=uint8, 2=float32

// ---------------------------------------------------------------------------
// PTX helpers
// ---------------------------------------------------------------------------
__device__ __forceinline__ void mma16816(float c[4], const uint32_t a[4],
                                         uint32_t b0, uint32_t b1) {
    asm volatile(
        "mma.sync.aligned.m16n8k16.row.col.f32.bf16.bf16.f32 "
        "{%0,%1,%2,%3}, {%4,%5,%6,%7}, {%8,%9}, {%0,%1,%2,%3};\n"
        : "+f"(c[0]), "+f"(c[1]), "+f"(c[2]), "+f"(c[3])
        : "r"(a[0]), "r"(a[1]), "r"(a[2]), "r"(a[3]), "r"(b0), "r"(b1));
}

__device__ __forceinline__ void ldsm_x2_t(uint32_t& r0, uint32_t& r1, uint32_t addr) {
    asm volatile("ldmatrix.sync.aligned.m8n8.x2.trans.shared.b16 {%0,%1}, [%2];\n"
                 : "=r"(r0), "=r"(r1) : "r"(addr));
}

__device__ __forceinline__ uint32_t pack_bf16(float lo, float hi) {
    __nv_bfloat162 t = __floats2bfloat162_rn(lo, hi);   // x=lo (low 16), y=hi
    return *reinterpret_cast<uint32_t*>(&t);
}

// ---------------------------------------------------------------------------
// Mask dtype probe (first 16KB of the buffer)
// ---------------------------------------------------------------------------
__global__ void probe_mask_kernel(const uint4* __restrict__ m) {
    __shared__ int s_flags;
    if (threadIdx.x == 0) s_flags = 0;
    __syncthreads();
    uint4 v = m[threadIdx.x];
    unsigned int ws[4] = {v.x, v.y, v.z, v.w};
    int f = 0;
    #pragma unroll
    for (int i = 0; i < 4; i++) {
        unsigned int w = ws[i];
        if (w > 1u)                      f |= 1;
        if ((w & 0xFEFEFEFEu) != 0u)     f |= 2;
        if (w != 0u && w != 0x3F800000u) f |= 4;
    }
    if (f) atomicOr(&s_flags, f);
    __syncthreads();
    if (threadIdx.x == 0) {
        int fl = s_flags, mode;
        if      (!(fl & 1)) mode = 0;
        else if (!(fl & 2)) mode = 1;
        else if (!(fl & 4)) mode = 2;
        else                mode = 1;
        g_mask_mode = mode;
    }
}

// ---------------------------------------------------------------------------
// fp32 [R][C] -> bf16 transposed [C][R]
// ---------------------------------------------------------------------------
__global__ void transpose_to_bf16(const float* __restrict__ in,
                                  __nv_bfloat16* __restrict__ out, int R, int C) {
    __shared__ float t[32][33];
    int bx = blockIdx.x * 32, by = blockIdx.y * 32;
    int tx = threadIdx.x, ty = threadIdx.y;
    #pragma unroll
    for (int j = 0; j < 32; j += 8)
        t[ty + j][tx] = in[(size_t)(by + ty + j) * C + bx + tx];
    __syncthreads();
    #pragma unroll
    for (int j = 0; j < 32; j += 8)
        out[(size_t)(bx + ty + j) * R + by + tx] = __float2bfloat16(t[tx][ty + j]);
}

// ---------------------------------------------------------------------------
// bf16 tensor-core GEMM: C[M,N] = A[M,K] @ Bt[N,K]^T + bias (+resid)
// 128x128x32 CTA tile, 8 warps of 32x64. A_BF16: A dtype; OUT_BF16: C dtype.
// ---------------------------------------------------------------------------
template<int A_BF16, int OUT_BF16>
__global__ __launch_bounds__(256, 2) void gemm_bf16(
    const void* __restrict__ A, const __nv_bfloat16* __restrict__ Bt,
    const float* __restrict__ bias, const float* __restrict__ resid,
    void* __restrict__ C, int M, int N, int K)
{
    __shared__ __nv_bfloat16 As[128 * 40];   // [m][k], stride 40
    __shared__ __nv_bfloat16 Bs[128 * 40];   // [n][k], stride 40

    const int tid = threadIdx.x;
    const int wid = tid >> 5, lane = tid & 31;
    const int g = lane >> 2, tg = lane & 3;
    const int wm = wid >> 1, wn = wid & 1;
    const int row0 = blockIdx.y * 128, col0 = blockIdx.x * 128;
    const int m0 = wm * 32, n0 = wn * 64;

    float acc[2][8][4];
    #pragma unroll
    for (int i = 0; i < 2; i++)
        #pragma unroll
        for (int j = 0; j < 8; j++)
            #pragma unroll
            for (int c = 0; c < 4; c++) acc[i][j][c] = 0.f;

    for (int kt = 0; kt < K; kt += 32) {
        if (A_BF16) {
            #pragma unroll
            for (int i = 0; i < 2; i++) {
                int idx = tid + i * 256;
                int r = idx >> 2, kc = (idx & 3) * 8;
                *(uint4*)&As[r * 40 + kc] =
                    *(const uint4*)((const __nv_bfloat16*)A + (size_t)(row0 + r) * K + kt + kc);
            }
        } else {
            #pragma unroll
            for (int i = 0; i < 4; i++) {
                int idx = tid + i * 256;
                int r = idx >> 3, kc = (idx & 7) * 4;
                float4 v = *(const float4*)((const float*)A + (size_t)(row0 + r) * K + kt + kc);
                *(__nv_bfloat162*)&As[r * 40 + kc]     = __floats2bfloat162_rn(v.x, v.y);
                *(__nv_bfloat162*)&As[r * 40 + kc + 2] = __floats2bfloat162_rn(v.z, v.w);
            }
        }
        #pragma unroll
        for (int i = 0; i < 2; i++) {
            int idx = tid + i * 256;
            int n = idx >> 2, kc = (idx & 3) * 8;
            *(uint4*)&Bs[n * 40 + kc] =
                *(const uint4*)&Bt[(size_t)(col0 + n) * K + kt + kc];
        }
        __syncthreads();

        #pragma unroll
        for (int ks = 0; ks < 2; ks++) {
            int k16 = ks * 16;
            uint32_t af[2][4];
            #pragma unroll
            for (int mt = 0; mt < 2; mt++) {
                const __nv_bfloat16* ap = &As[(m0 + mt * 16 + g) * 40 + k16 + tg * 2];
                af[mt][0] = *(const uint32_t*)ap;
                af[mt][1] = *(const uint32_t*)(ap + 8 * 40);
                af[mt][2] = *(const uint32_t*)(ap + 8);
                af[mt][3] = *(const uint32_t*)(ap + 8 * 40 + 8);
            }
            #pragma unroll
            for (int nt = 0; nt < 8; nt++) {
                const __nv_bfloat16* bp = &Bs[(n0 + nt * 8 + g) * 40 + k16 + tg * 2];
                uint32_t b0 = *(const uint32_t*)bp;
                uint32_t b1 = *(const uint32_t*)(bp + 8);
                mma16816(acc[0][nt], af[0], b0, b1);
                mma16816(acc[1][nt], af[1], b0, b1);
            }
        }
        __syncthreads();
    }

    #pragma unroll
    for (int mt = 0; mt < 2; mt++) {
        #pragma unroll
        for (int half = 0; half < 2; half++) {
            int r = row0 + m0 + mt * 16 + g + half * 8;
            #pragma unroll
            for (int nt = 0; nt < 8; nt++) {
                int c = col0 + n0 + nt * 8 + tg * 2;
                float v0 = acc[mt][nt][half * 2 + 0] + bias[c];
                float v1 = acc[mt][nt][half * 2 + 1] + bias[c + 1];
                if (OUT_BF16) {
                    *(__nv_bfloat162*)((__nv_bfloat16*)C + (size_t)r * N + c) =
                        __floats2bfloat162_rn(v0, v1);
                } else {
                    float2 rv = *(const float2*)&resid[(size_t)r * N + c];
                    float2 o = make_float2(v0 + rv.x, v1 + rv.y);
                    *(float2*)((float*)C + (size_t)r * N + c) = o;
                }
            }
        }
    }
}

// ---------------------------------------------------------------------------
// FA2-style attention: CTA = 128 q-rows of one (b,h); 8 warps x m16 x n64.
// Q frags in regs (prescaled 1/8); S/softmax/P in regs; K,V bf16 in smem.
// ---------------------------------------------------------------------------
__global__ __launch_bounds__(256, 2) void attn_kernel(
    const void* __restrict__ mask, __nv_bfloat16* __restrict__ ctx)
{
    __shared__ __nv_bfloat16 Ks[64 * 72];   // [token][d]
    __shared__ __nv_bfloat16 Vs[64 * 72];   // [token][d]

    const int tid = threadIdx.x;
    const int wid = tid >> 5, lane = tid & 31;
    const int g = lane >> 2, tg = lane & 3;
    const int q0 = blockIdx.x * 128;
    const int h = blockIdx.y, b = blockIdx.z;
    const int mmode = g_mask_mode;
    const int qrow = q0 + wid * 16 + g;                 // rows qrow, qrow+8
    const size_t qbase = (size_t)(b * SS + qrow) * QKVC + h * 192;

    // Q fragments (prescaled by 0.125, exact in bf16)
    uint32_t qa[4][4];
    const __nv_bfloat162 sc = __floats2bfloat162_rn(0.125f, 0.125f);
    #pragma unroll
    for (int t = 0; t < 4; t++) {
        int d = t * 16 + tg * 2;
        __nv_bfloat162 v;
        v = __hmul2(*(const __nv_bfloat162*)&g_qkvh[qbase + d], sc);
        qa[t][0] = *reinterpret_cast<uint32_t*>(&v);
        v = __hmul2(*(const __nv_bfloat162*)&g_qkvh[qbase + (size_t)8 * QKVC + d], sc);
        qa[t][1] = *reinterpret_cast<uint32_t*>(&v);
        v = __hmul2(*(const __nv_bfloat162*)&g_qkvh[qbase + d + 8], sc);
        qa[t][2] = *reinterpret_cast<uint32_t*>(&v);
        v = __hmul2(*(const __nv_bfloat162*)&g_qkvh[qbase + (size_t)8 * QKVC + d + 8], sc);
        qa[t][3] = *reinterpret_cast<uint32_t*>(&v);
    }

    float O[8][4];
    #pragma unroll
    for (int nt = 0; nt < 8; nt++)
        #pragma unroll
        for (int c = 0; c < 4; c++) O[nt][c] = 0.f;
    float mstat[2] = {NEG_INF, NEG_INF};
    float lstat[2] = {0.f, 0.f};

    for (int kt = 0; kt < SS; kt += 64) {
        __syncthreads();
        #pragma unroll
        for (int i = 0; i < 2; i++) {
            int idx = tid + i * 256;
            int tok = idx >> 3, dc = (idx & 7) * 8;
            size_t base = (size_t)(b * SS + kt + tok) * QKVC + h * 192;
            *(uint4*)&Ks[tok * 72 + dc] = *(const uint4*)&g_qkvh[base + 64 + dc];
            *(uint4*)&Vs[tok * 72 + dc] = *(const uint4*)&g_qkvh[base + 128 + dc];
        }
        __syncthreads();

        // S = (Q/8) @ K^T
        float s[8][4];
        #pragma unroll
        for (int nt = 0; nt < 8; nt++)
            #pragma unroll
            for (int c = 0; c < 4; c++) s[nt][c] = 0.f;
        #pragma unroll
        for (int t = 0; t < 4; t++) {
            #pragma unroll
            for (int nt = 0; nt < 8; nt++) {
                const __nv_bfloat16* bp = &Ks[(nt * 8 + g) * 72 + t * 16 + tg * 2];
                uint32_t b0 = *(const uint32_t*)bp;
                uint32_t b1 = *(const uint32_t*)(bp + 8);
                mma16816(s[nt], qa[t], b0, b1);
            }
        }

        // mask  (layout [b][q][h][k])
        #pragma unroll
        for (int r = 0; r < 2; r++) {
            size_t mrow = ((size_t)(b * SS + qrow + r * 8) * NHEAD + h) * SS + kt;
            #pragma unroll
            for (int nt = 0; nt < 8; nt++) {
                int kc = nt * 8 + tg * 2;
                bool mk0, mk1;
                if (mmode == 0) {
                    int2 v = *(const int2*)((const int*)mask + mrow + kc);
                    mk0 = v.x != 0; mk1 = v.y != 0;
                } else if (mmode == 1) {
                    const unsigned char* mp = (const unsigned char*)mask + mrow + kc;
                    mk0 = mp[0] != 0; mk1 = mp[1] != 0;
                } else {
                    float2 v = *(const float2*)((const float*)mask + mrow + kc);
                    mk0 = v.x != 0.f; mk1 = v.y != 0.f;
                }
                if (!mk0) s[nt][r * 2 + 0] = NEG_INF;
                if (!mk1) s[nt][r * 2 + 1] = NEG_INF;
            }
        }

        // online softmax (registers + tig-quad shfl)
        float alpha[2];
        #pragma unroll
        for (int r = 0; r < 2; r++) {
            float mloc = NEG_INF;
            #pragma unroll
            for (int nt = 0; nt < 8; nt++)
                mloc = fmaxf(mloc, fmaxf(s[nt][r * 2], s[nt][r * 2 + 1]));
            mloc = fmaxf(mloc, __shfl_xor_sync(0xffffffffu, mloc, 1));
            mloc = fmaxf(mloc, __shfl_xor_sync(0xffffffffu, mloc, 2));
            float mnew = fmaxf(mstat[r], mloc);
            float a = (mnew == NEG_INF) ? 1.f : __expf(mstat[r] - mnew);
            float sum = 0.f;
            #pragma unroll
            for (int nt = 0; nt < 8; nt++) {
                #pragma unroll
                for (int j = 0; j < 2; j++) {
                    float sv = s[nt][r * 2 + j];
                    float p = (sv == NEG_INF) ? 0.f : __expf(sv - mnew);
                    s[nt][r * 2 + j] = p;
                    sum += p;
                }
            }
            sum += __shfl_xor_sync(0xffffffffu, sum, 1);
            sum += __shfl_xor_sync(0xffffffffu, sum, 2);
            lstat[r] = lstat[r] * a + sum;
            mstat[r] = mnew;
            alpha[r] = a;
        }
        #pragma unroll
        for (int nt = 0; nt < 8; nt++) {
            O[nt][0] *= alpha[0]; O[nt][1] *= alpha[0];
            O[nt][2] *= alpha[1]; O[nt][3] *= alpha[1];
        }

        // O += P @ V   (P frags straight from S registers; V via ldmatrix.trans)
        #pragma unroll
        for (int t = 0; t < 4; t++) {
            uint32_t pa[4];
            pa[0] = pack_bf16(s[2 * t][0],     s[2 * t][1]);
            pa[1] = pack_bf16(s[2 * t][2],     s[2 * t][3]);
            pa[2] = pack_bf16(s[2 * t + 1][0], s[2 * t + 1][1]);
            pa[3] = pack_bf16(s[2 * t + 1][2], s[2 * t + 1][3]);
            int vrow = 16 * t + (lane & 15);
            #pragma unroll
            for (int nt = 0; nt < 8; nt++) {
                uint32_t saddr =
                    (uint32_t)__cvta_generic_to_shared(&Vs[vrow * 72 + nt * 8]);
                uint32_t b0, b1;
                ldsm_x2_t(b0, b1, saddr);
                mma16816(O[nt], pa, b0, b1);
            }
        }
    }

    // normalize + write ctx (bf16)
    float linv0 = (lstat[0] > 0.f) ? (1.f / lstat[0]) : 0.f;
    float linv1 = (lstat[1] > 0.f) ? (1.f / lstat[1]) : 0.f;
    size_t obase0 = (size_t)(b * SS + qrow) * NHID + h * 64 + tg * 2;
    size_t obase1 = obase0 + (size_t)8 * NHID;
    #pragma unroll
    for (int nt = 0; nt < 8; nt++) {
        *(uint32_t*)&ctx[obase0 + nt * 8] = pack_bf16(O[nt][0] * linv0, O[nt][1] * linv0);
        *(uint32_t*)&ctx[obase1 + nt * 8] = pack_bf16(O[nt][2] * linv1, O[nt][3] * linv1);
    }
}

// ---------------------------------------------------------------------------
extern "C" void kernel_launch(void* const* d_in, const int* in_sizes, int n_in,
                              void* d_out, int out_size)
{
    const float* x     = (const float*)d_in[0];
    const void*  mask  = d_in[1];
    const float* W_qkv = (const float*)d_in[2];
    const float* b_qkv = (const float*)d_in[3];
    const float* W_out = (const float*)d_in[4];
    const float* b_out = (const float*)d_in[5];
    float*       out   = (float*)d_out;

    __nv_bfloat16 *qkvh, *ctxh, *wqkvt, *woutt;
    cudaGetSymbolAddress((void**)&qkvh,  g_qkvh);
    cudaGetSymbolAddress((void**)&ctxh,  g_ctxh);
    cudaGetSymbolAddress((void**)&wqkvt, g_wqkvt);
    cudaGetSymbolAddress((void**)&woutt, g_woutt);

    // 0) Weight transposes to bf16 [N][K] + mask dtype probe
    transpose_to_bf16<<<dim3(QKVC / 32, NHID / 32), dim3(32, 8)>>>(W_qkv, wqkvt, NHID, QKVC);
    transpose_to_bf16<<<dim3(NHID / 32, NHID / 32), dim3(32, 8)>>>(W_out, woutt, NHID, NHID);
    probe_mask_kernel<<<1, 1024>>>((const uint4*)mask);

    // 1) QKV projection (fp32 in, bf16 out)
    gemm_bf16<0, 1><<<dim3(QKVC / 128, ROWS / 128), 256>>>(
        x, wqkvt, b_qkv, nullptr, qkvh, ROWS, QKVC, NHID);

    // 2) Masked flash attention (bf16 tensor cores)
    attn_kernel<<<dim3(SS / 128, NHEAD, BB), 256>>>(mask, ctxh);

    // 3) Output projection + bias + residual (bf16 in, fp32 out)
    gemm_bf16<1, 0><<<dim3(NHID / 128, ROWS / 128), 256>>>(
        ctxh, woutt, b_out, x, out, ROWS, NHID, NHID);
}

// round 9
// speedup vs baseline: 6.7827x; 1.2020x over previous
#include <cuda_runtime.h>
#include <cuda_bf16.h>
#include <cstdint>
#include <cstddef>

#define NHID 1024
#define NHEAD 16
#define BB   2
#define SS   2048
#define QKVC 3072              // NHEAD * (2*64 + 64)
#define ROWS (BB*SS)           // 4096

#define NEG_INF (__int_as_float(0xff800000))

// Scratch (allocation-free rule: device globals)
__device__ __nv_bfloat16 g_xh[(size_t)ROWS * NHID];     // x in bf16
__device__ __nv_bfloat16 g_qkvh[(size_t)ROWS * QKVC];   // [row][h*192 + {q,k,v}]
__device__ __nv_bfloat16 g_ctxh[(size_t)ROWS * NHID];   // [row][h*64 + d]
__device__ __nv_bfloat16 g_wqkvt[(size_t)QKVC * NHID];  // W_qkv^T  [n][k] bf16
__device__ __nv_bfloat16 g_woutt[(size_t)NHID * NHID];  // W_out^T  [n][k] bf16
__device__ int g_mask_mode;                             // 0=int32, 1=uint8, 2=float32

// ---------------------------------------------------------------------------
// PTX helpers
// ---------------------------------------------------------------------------
__device__ __forceinline__ void mma16816(float c[4], const uint32_t a[4],
                                         uint32_t b0, uint32_t b1) {
    asm volatile(
        "mma.sync.aligned.m16n8k16.row.col.f32.bf16.bf16.f32 "
        "{%0,%1,%2,%3}, {%4,%5,%6,%7}, {%8,%9}, {%0,%1,%2,%3};\n"
        : "+f"(c[0]), "+f"(c[1]), "+f"(c[2]), "+f"(c[3])
        : "r"(a[0]), "r"(a[1]), "r"(a[2]), "r"(a[3]), "r"(b0), "r"(b1));
}

__device__ __forceinline__ void ldsm_x4(uint32_t& r0, uint32_t& r1,
                                        uint32_t& r2, uint32_t& r3, uint32_t addr) {
    asm volatile("ldmatrix.sync.aligned.m8n8.x4.shared.b16 {%0,%1,%2,%3}, [%4];\n"
                 : "=r"(r0), "=r"(r1), "=r"(r2), "=r"(r3) : "r"(addr));
}

__device__ __forceinline__ void ldsm_x4_t(uint32_t& r0, uint32_t& r1,
                                          uint32_t& r2, uint32_t& r3, uint32_t addr) {
    asm volatile("ldmatrix.sync.aligned.m8n8.x4.trans.shared.b16 {%0,%1,%2,%3}, [%4];\n"
                 : "=r"(r0), "=r"(r1), "=r"(r2), "=r"(r3) : "r"(addr));
}

#define CP_ASYNC16(dst, src) \
    asm volatile("cp.async.cg.shared.global [%0], [%1], 16;\n" :: "r"(dst), "l"(src))
#define CP_COMMIT() asm volatile("cp.async.commit_group;\n" ::: "memory")
#define CP_WAIT1()  asm volatile("cp.async.wait_group 1;\n" ::: "memory")

__device__ __forceinline__ uint32_t sptr(const void* p) {
    return (uint32_t)__cvta_generic_to_shared(p);
}

__device__ __forceinline__ uint32_t pack_bf16(float lo, float hi) {
    __nv_bfloat162 t = __floats2bfloat162_rn(lo, hi);
    return *reinterpret_cast<uint32_t*>(&t);
}

// ---------------------------------------------------------------------------
// Mask dtype probe (first 16KB of the buffer)
// ---------------------------------------------------------------------------
__global__ void probe_mask_kernel(const uint4* __restrict__ m) {
    __shared__ int s_flags;
    if (threadIdx.x == 0) s_flags = 0;
    __syncthreads();
    uint4 v = m[threadIdx.x];
    unsigned int ws[4] = {v.x, v.y, v.z, v.w};
    int f = 0;
    #pragma unroll
    for (int i = 0; i < 4; i++) {
        unsigned int w = ws[i];
        if (w > 1u)                      f |= 1;
        if ((w & 0xFEFEFEFEu) != 0u)     f |= 2;
        if (w != 0u && w != 0x3F800000u) f |= 4;
    }
    if (f) atomicOr(&s_flags, f);
    __syncthreads();
    if (threadIdx.x == 0) {
        int fl = s_flags, mode;
        if      (!(fl & 1)) mode = 0;
        else if (!(fl & 2)) mode = 1;
        else if (!(fl & 4)) mode = 2;
        else                mode = 1;
        g_mask_mode = mode;
    }
}

// ---------------------------------------------------------------------------
// Prep: fp32 -> bf16 (flat), and fp32 [R][C] -> bf16 transposed [C][R]
// ---------------------------------------------------------------------------
__global__ void f32_to_bf16(const float* __restrict__ in,
                            __nv_bfloat16* __restrict__ out, int n4) {
    int i = blockIdx.x * blockDim.x + threadIdx.x;
    if (i < n4) {
        float4 v = *(const float4*)(in + (size_t)i * 4);
        __nv_bfloat162 a = __floats2bfloat162_rn(v.x, v.y);
        __nv_bfloat162 b = __floats2bfloat162_rn(v.z, v.w);
        uint2 o = make_uint2(*(uint32_t*)&a, *(uint32_t*)&b);
        *(uint2*)(out + (size_t)i * 4) = o;
    }
}

__global__ void transpose_to_bf16(const float* __restrict__ in,
                                  __nv_bfloat16* __restrict__ out, int R, int C) {
    __shared__ float t[32][33];
    int bx = blockIdx.x * 32, by = blockIdx.y * 32;
    int tx = threadIdx.x, ty = threadIdx.y;
    #pragma unroll
    for (int j = 0; j < 32; j += 8)
        t[ty + j][tx] = in[(size_t)(by + ty + j) * C + bx + tx];
    __syncthreads();
    #pragma unroll
    for (int j = 0; j < 32; j += 8)
        out[(size_t)(bx + ty + j) * R + by + tx] = __float2bfloat16(t[tx][ty + j]);
}

// ---------------------------------------------------------------------------
// bf16 TC GEMM: C[M,N] = A[M,K] @ Bt[N,K]^T + bias (+resid)
// 128x128x32 CTA tile, 8 warps of 32x64, cp.async 2-stage, ldmatrix frags.
// ---------------------------------------------------------------------------
template<int OUT_BF16>
__global__ __launch_bounds__(256) void gemm_bf16(
    const __nv_bfloat16* __restrict__ A, const __nv_bfloat16* __restrict__ Bt,
    const float* __restrict__ bias, const float* __restrict__ resid,
    void* __restrict__ C, int M, int N, int K)
{
    __shared__ __nv_bfloat16 As[2][128 * 40];
    __shared__ __nv_bfloat16 Bs[2][128 * 40];

    const int tid = threadIdx.x;
    const int wid = tid >> 5, lane = tid & 31;
    const int g = lane >> 2, tg = lane & 3;
    const int wm = wid >> 1, wn = wid & 1;
    const int row0 = blockIdx.y * 128, col0 = blockIdx.x * 128;
    const int m0 = wm * 32, n0 = wn * 64;

    // ldmatrix lane offsets
    const int la_row = lane & 15,  la_k = (lane >> 4) * 8;               // A x4
    const int lb_row = (lane & 7) + (lane >> 4) * 8;                     // B x4
    const int lb_k   = ((lane >> 3) & 1) * 8;

    float acc[2][8][4];
    #pragma unroll
    for (int i = 0; i < 2; i++)
        #pragma unroll
        for (int j = 0; j < 8; j++)
            #pragma unroll
            for (int c = 0; c < 4; c++) acc[i][j][c] = 0.f;

    auto issue = [&](int stage, int kt) {
        #pragma unroll
        for (int i = 0; i < 2; i++) {
            int idx = tid + i * 256;
            int r = idx >> 2, sg = (idx & 3) * 8;
            CP_ASYNC16(sptr(&As[stage][r * 40 + sg]),
                       A + (size_t)(row0 + r) * K + kt + sg);
            CP_ASYNC16(sptr(&Bs[stage][r * 40 + sg]),
                       Bt + (size_t)(col0 + r) * K + kt + sg);
        }
    };

    const int NT = K / 32;
    issue(0, 0);  CP_COMMIT();
    issue(1, 32); CP_COMMIT();

    for (int i = 0; i < NT; i++) {
        CP_WAIT1();
        __syncthreads();
        const __nv_bfloat16* as = As[i & 1];
        const __nv_bfloat16* bs = Bs[i & 1];

        #pragma unroll
        for (int ks = 0; ks < 2; ks++) {
            int k16 = ks * 16;
            uint32_t a[2][4];
            #pragma unroll
            for (int mt = 0; mt < 2; mt++)
                ldsm_x4(a[mt][0], a[mt][1], a[mt][2], a[mt][3],
                        sptr(&as[(m0 + mt * 16 + la_row) * 40 + k16 + la_k]));
            #pragma unroll
            for (int p = 0; p < 4; p++) {
                uint32_t b0, b1, b2, b3;
                ldsm_x4(b0, b1, b2, b3,
                        sptr(&bs[(n0 + p * 16 + lb_row) * 40 + k16 + lb_k]));
                mma16816(acc[0][2 * p],     a[0], b0, b1);
                mma16816(acc[1][2 * p],     a[1], b0, b1);
                mma16816(acc[0][2 * p + 1], a[0], b2, b3);
                mma16816(acc[1][2 * p + 1], a[1], b2, b3);
            }
        }
        __syncthreads();
        if (i + 2 < NT) issue(i & 1, (i + 2) * 32);
        CP_COMMIT();
    }

    #pragma unroll
    for (int mt = 0; mt < 2; mt++) {
        #pragma unroll
        for (int half = 0; half < 2; half++) {
            int r = row0 + m0 + mt * 16 + g + half * 8;
            #pragma unroll
            for (int nt = 0; nt < 8; nt++) {
                int c = col0 + n0 + nt * 8 + tg * 2;
                float v0 = acc[mt][nt][half * 2 + 0] + bias[c];
                float v1 = acc[mt][nt][half * 2 + 1] + bias[c + 1];
                if (OUT_BF16) {
                    *(__nv_bfloat162*)((__nv_bfloat16*)C + (size_t)r * N + c) =
                        __floats2bfloat162_rn(v0, v1);
                } else {
                    float2 rv = *(const float2*)&resid[(size_t)r * N + c];
                    *(float2*)((float*)C + (size_t)r * N + c) =
                        make_float2(v0 + rv.x, v1 + rv.y);
                }
            }
        }
    }
}

// ---------------------------------------------------------------------------
// FA2 attention: CTA = 128 q-rows of one (b,h); 8 warps x m16 x n64.
// cp.async 2-stage K/V, ldmatrix frags, mask prefetch, branch-free softmax.
// ---------------------------------------------------------------------------
__global__ __launch_bounds__(256) void attn_kernel(
    const void* __restrict__ mask, __nv_bfloat16* __restrict__ ctx)
{
    __shared__ __nv_bfloat16 Ks[2][64 * 72];
    __shared__ __nv_bfloat16 Vs[2][64 * 72];

    const int tid = threadIdx.x;
    const int wid = tid >> 5, lane = tid & 31;
    const int g = lane >> 2, tg = lane & 3;
    const int q0 = blockIdx.x * 128;
    const int h = blockIdx.y, b = blockIdx.z;
    const int mmode = g_mask_mode;
    const int qrow = q0 + wid * 16 + g;
    const size_t qbase = (size_t)(b * SS + qrow) * QKVC + h * 192;

    // ldmatrix lane offsets
    const int lk_row = (lane & 7) + (lane >> 4) * 8;         // K x4 (B-type)
    const int lk_k   = ((lane >> 3) & 1) * 8;
    const int lv_row = (lane & 7) + ((lane >> 3) & 1) * 8;   // V x4.trans
    const int lv_c   = (lane >> 4) * 8;

    auto issueKV = [&](int stage, int kt) {
        #pragma unroll
        for (int i = 0; i < 2; i++) {
            int idx = tid + i * 256;
            int tok = idx >> 3, sg = (idx & 7) * 8;
            const __nv_bfloat16* src =
                g_qkvh + (size_t)(b * SS + kt + tok) * QKVC + h * 192;
            CP_ASYNC16(sptr(&Ks[stage][tok * 72 + sg]), src + 64 + sg);
            CP_ASYNC16(sptr(&Vs[stage][tok * 72 + sg]), src + 128 + sg);
        }
    };

    issueKV(0, 0);  CP_COMMIT();
    issueKV(1, 64); CP_COMMIT();

    // Q fragments (prescaled by 0.125, exact in bf16)
    uint32_t qa[4][4];
    const __nv_bfloat162 sc = __floats2bfloat162_rn(0.125f, 0.125f);
    #pragma unroll
    for (int t = 0; t < 4; t++) {
        int d = t * 16 + tg * 2;
        __nv_bfloat162 v;
        v = __hmul2(*(const __nv_bfloat162*)&g_qkvh[qbase + d], sc);
        qa[t][0] = *reinterpret_cast<uint32_t*>(&v);
        v = __hmul2(*(const __nv_bfloat162*)&g_qkvh[qbase + (size_t)8 * QKVC + d], sc);
        qa[t][1] = *reinterpret_cast<uint32_t*>(&v);
        v = __hmul2(*(const __nv_bfloat162*)&g_qkvh[qbase + d + 8], sc);
        qa[t][2] = *reinterpret_cast<uint32_t*>(&v);
        v = __hmul2(*(const __nv_bfloat162*)&g_qkvh[qbase + (size_t)8 * QKVC + d + 8], sc);
        qa[t][3] = *reinterpret_cast<uint32_t*>(&v);
    }

    float O[8][4];
    #pragma unroll
    for (int nt = 0; nt < 8; nt++)
        #pragma unroll
        for (int c = 0; c < 4; c++) O[nt][c] = 0.f;
    float mstat[2] = {-1e30f, -1e30f};
    float lstat[2] = {0.f, 0.f};

    for (int it = 0; it < SS / 64; it++) {
        const int kt = it * 64;
        CP_WAIT1();
        __syncthreads();
        const __nv_bfloat16* ks = Ks[it & 1];
        const __nv_bfloat16* vs = Vs[it & 1];

        // Prefetch mask into packed regs (LDG hidden under S MMAs)
        uint32_t mpk[2][8];
        #pragma unroll
        for (int r = 0; r < 2; r++) {
            size_t mrow = ((size_t)(b * SS + qrow + r * 8) * NHEAD + h) * SS + kt;
            #pragma unroll
            for (int nt = 0; nt < 8; nt++) {
                int kc = nt * 8 + tg * 2;
                if (mmode == 0) {
                    int2 v = *(const int2*)((const int*)mask + mrow + kc);
                    mpk[r][nt] = (v.x ? 1u : 0u) | (v.y ? 2u : 0u);
                } else if (mmode == 1) {
                    const unsigned char* mp = (const unsigned char*)mask + mrow + kc;
                    mpk[r][nt] = (mp[0] ? 1u : 0u) | (mp[1] ? 2u : 0u);
                } else {
                    float2 v = *(const float2*)((const float*)mask + mrow + kc);
                    mpk[r][nt] = (v.x != 0.f ? 1u : 0u) | (v.y != 0.f ? 2u : 0u);
                }
            }
        }

        // S = (Q/8) @ K^T
        float s[8][4];
        #pragma unroll
        for (int nt = 0; nt < 8; nt++)
            #pragma unroll
            for (int c = 0; c < 4; c++) s[nt][c] = 0.f;
        #pragma unroll
        for (int t = 0; t < 4; t++) {
            #pragma unroll
            for (int p = 0; p < 4; p++) {
                uint32_t b0, b1, b2, b3;
                ldsm_x4(b0, b1, b2, b3,
                        sptr(&ks[(p * 16 + lk_row) * 72 + t * 16 + lk_k]));
                mma16816(s[2 * p],     qa[t], b0, b1);
                mma16816(s[2 * p + 1], qa[t], b2, b3);
            }
        }

        // apply mask
        #pragma unroll
        for (int r = 0; r < 2; r++)
            #pragma unroll
            for (int nt = 0; nt < 8; nt++) {
                if (!(mpk[r][nt] & 1u)) s[nt][r * 2 + 0] = NEG_INF;
                if (!(mpk[r][nt] & 2u)) s[nt][r * 2 + 1] = NEG_INF;
            }

        // online softmax (branch-free; running max clamped at -1e30)
        float alpha[2];
        #pragma unroll
        for (int r = 0; r < 2; r++) {
            float mloc = NEG_INF;
            #pragma unroll
            for (int nt = 0; nt < 8; nt++)
                mloc = fmaxf(mloc, fmaxf(s[nt][r * 2], s[nt][r * 2 + 1]));
            mloc = fmaxf(mloc, __shfl_xor_sync(0xffffffffu, mloc, 1));
            mloc = fmaxf(mloc, __shfl_xor_sync(0xffffffffu, mloc, 2));
            float mnew = fmaxf(mstat[r], mloc);
            float a = __expf(mstat[r] - mnew);
            float sum = 0.f;
            #pragma unroll
            for (int nt = 0; nt < 8; nt++) {
                #pragma unroll
                for (int j = 0; j < 2; j++) {
                    float p = __expf(s[nt][r * 2 + j] - mnew);  // exp(-inf)=0
                    s[nt][r * 2 + j] = p;
                    sum += p;
                }
            }
            sum += __shfl_xor_sync(0xffffffffu, sum, 1);
            sum += __shfl_xor_sync(0xffffffffu, sum, 2);
            lstat[r] = lstat[r] * a + sum;
            mstat[r] = mnew;
            alpha[r] = a;
        }
        #pragma unroll
        for (int nt = 0; nt < 8; nt++) {
            O[nt][0] *= alpha[0]; O[nt][1] *= alpha[0];
            O[nt][2] *= alpha[1]; O[nt][3] *= alpha[1];
        }

        // O += P @ V
        #pragma unroll
        for (int t = 0; t < 4; t++) {
            uint32_t pa[4];
            pa[0] = pack_bf16(s[2 * t][0],     s[2 * t][1]);
            pa[1] = pack_bf16(s[2 * t][2],     s[2 * t][3]);
            pa[2] = pack_bf16(s[2 * t + 1][0], s[2 * t + 1][1]);
            pa[3] = pack_bf16(s[2 * t + 1][2], s[2 * t + 1][3]);
            #pragma unroll
            for (int p = 0; p < 4; p++) {
                uint32_t b0, b1, b2, b3;
                ldsm_x4_t(b0, b1, b2, b3,
                          sptr(&vs[(16 * t + lv_row) * 72 + p * 16 + lv_c]));
                mma16816(O[2 * p],     pa, b0, b1);
                mma16816(O[2 * p + 1], pa, b2, b3);
            }
        }

        __syncthreads();
        if (kt + 128 < SS) issueKV(it & 1, kt + 128);
        CP_COMMIT();
    }

    // normalize + write ctx (bf16)
    float linv0 = (lstat[0] > 0.f) ? (1.f / lstat[0]) : 0.f;
    float linv1 = (lstat[1] > 0.f) ? (1.f / lstat[1]) : 0.f;
    size_t obase0 = (size_t)(b * SS + qrow) * NHID + h * 64 + tg * 2;
    size_t obase1 = obase0 + (size_t)8 * NHID;
    #pragma unroll
    for (int nt = 0; nt < 8; nt++) {
        *(uint32_t*)&ctx[obase0 + nt * 8] = pack_bf16(O[nt][0] * linv0, O[nt][1] * linv0);
        *(uint32_t*)&ctx[obase1 + nt * 8] = pack_bf16(O[nt][2] * linv1, O[nt][3] * linv1);
    }
}

// ---------------------------------------------------------------------------
extern "C" void kernel_launch(void* const* d_in, const int* in_sizes, int n_in,
                              void* d_out, int out_size)
{
    const float* x     = (const float*)d_in[0];
    const void*  mask  = d_in[1];
    const float* W_qkv = (const float*)d_in[2];
    const float* b_qkv = (const float*)d_in[3];
    const float* W_out = (const float*)d_in[4];
    const float* b_out = (const float*)d_in[5];
    float*       out   = (float*)d_out;

    __nv_bfloat16 *xh, *qkvh, *ctxh, *wqkvt, *woutt;
    cudaGetSymbolAddress((void**)&xh,    g_xh);
    cudaGetSymbolAddress((void**)&qkvh,  g_qkvh);
    cudaGetSymbolAddress((void**)&ctxh,  g_ctxh);
    cudaGetSymbolAddress((void**)&wqkvt, g_wqkvt);
    cudaGetSymbolAddress((void**)&woutt, g_woutt);

    // 0) Prep: weight transposes, x->bf16, mask dtype probe
    transpose_to_bf16<<<dim3(QKVC / 32, NHID / 32), dim3(32, 8)>>>(W_qkv, wqkvt, NHID, QKVC);
    transpose_to_bf16<<<dim3(NHID / 32, NHID / 32), dim3(32, 8)>>>(W_out, woutt, NHID, NHID);
    f32_to_bf16<<<(ROWS * NHID / 4 + 255) / 256, 256>>>(x, xh, ROWS * NHID / 4);
    probe_mask_kernel<<<1, 1024>>>((const uint4*)mask);

    // 1) QKV projection (bf16 in, bf16 out)
    gemm_bf16<1><<<dim3(QKVC / 128, ROWS / 128), 256>>>(
        xh, wqkvt, b_qkv, nullptr, qkvh, ROWS, QKVC, NHID);

    // 2) Masked flash attention (bf16 tensor cores)
    attn_kernel<<<dim3(SS / 128, NHEAD, BB), 256>>>(mask, ctxh);

    // 3) Output projection + bias + residual (bf16 in, fp32 out)
    gemm_bf16<0><<<dim3(NHID / 128, ROWS / 128), 256>>>(
        ctxh, woutt, b_out, x, out, ROWS, NHID, NHID);
}

// round 14
// speedup vs baseline: 6.8129x; 1.0045x over previous
#include <cuda_runtime.h>
#include <cuda_bf16.h>
#include <cstdint>
#include <cstddef>

#define NHID 1024
#define NHEAD 16
#define BB   2
#define SS   2048
#define QKVC 3072              // NHEAD * (2*64 + 64)
#define ROWS (BB*SS)           // 4096

#define NEG_INF (__int_as_float(0xff800000))

// Scratch (allocation-free rule: device globals)
__device__ __nv_bfloat16 g_xh[(size_t)ROWS * NHID];     // x in bf16
__device__ __nv_bfloat16 g_qkvh[(size_t)ROWS * QKVC];   // [row][h*192 + {q,k,v}]
__device__ __nv_bfloat16 g_ctxh[(size_t)ROWS * NHID];   // [row][h*64 + d]
__device__ __nv_bfloat16 g_wqkvt[(size_t)QKVC * NHID];  // W_qkv^T  [n][k] bf16
__device__ __nv_bfloat16 g_woutt[(size_t)NHID * NHID];  // W_out^T  [n][k] bf16
__device__ int g_mask_mode;                             // 0=int32, 1=uint8, 2=float32

// ---------------------------------------------------------------------------
// PTX helpers
// ---------------------------------------------------------------------------
__device__ __forceinline__ void mma16816(float c[4], const uint32_t a[4],
                                         uint32_t b0, uint32_t b1) {
    asm volatile(
        "mma.sync.aligned.m16n8k16.row.col.f32.bf16.bf16.f32 "
        "{%0,%1,%2,%3}, {%4,%5,%6,%7}, {%8,%9}, {%0,%1,%2,%3};\n"
        : "+f"(c[0]), "+f"(c[1]), "+f"(c[2]), "+f"(c[3])
        : "r"(a[0]), "r"(a[1]), "r"(a[2]), "r"(a[3]), "r"(b0), "r"(b1));
}

__device__ __forceinline__ void ldsm_x4(uint32_t& r0, uint32_t& r1,
                                        uint32_t& r2, uint32_t& r3, uint32_t addr) {
    asm volatile("ldmatrix.sync.aligned.m8n8.x4.shared.b16 {%0,%1,%2,%3}, [%4];\n"
                 : "=r"(r0), "=r"(r1), "=r"(r2), "=r"(r3) : "r"(addr));
}

__device__ __forceinline__ void ldsm_x4_t(uint32_t& r0, uint32_t& r1,
                                          uint32_t& r2, uint32_t& r3, uint32_t addr) {
    asm volatile("ldmatrix.sync.aligned.m8n8.x4.trans.shared.b16 {%0,%1,%2,%3}, [%4];\n"
                 : "=r"(r0), "=r"(r1), "=r"(r2), "=r"(r3) : "r"(addr));
}

#define CP_ASYNC16(dst, src) \
    asm volatile("cp.async.cg.shared.global [%0], [%1], 16;\n" :: "r"(dst), "l"(src))
#define CP_COMMIT() asm volatile("cp.async.commit_group;\n" ::: "memory")
#define CP_WAIT1()  asm volatile("cp.async.wait_group 1;\n" ::: "memory")

__device__ __forceinline__ uint32_t sptr(const void* p) {
    return (uint32_t)__cvta_generic_to_shared(p);
}

__device__ __forceinline__ uint32_t pack_bf16(float lo, float hi) {
    __nv_bfloat162 t = __floats2bfloat162_rn(lo, hi);
    return *reinterpret_cast<uint32_t*>(&t);
}

// ---------------------------------------------------------------------------
// Prep A: fused weight transposes (z=0: W_qkv, z=1: W_out), fp32 -> bf16 [C][R]
// ---------------------------------------------------------------------------
__global__ void prep_transpose(const float* __restrict__ w_qkv,
                               const float* __restrict__ w_out,
                               __nv_bfloat16* __restrict__ wqkvt,
                               __nv_bfloat16* __restrict__ woutt) {
    const float* in;
    __nv_bfloat16* out;
    int R = NHID, C;
    if (blockIdx.z == 0) { in = w_qkv; out = wqkvt; C = QKVC; }
    else                 { in = w_out; out = woutt; C = NHID; }
    int bx = blockIdx.x * 32, by = blockIdx.y * 32;
    if (bx >= C) return;
    __shared__ float t[32][33];
    int tx = threadIdx.x, ty = threadIdx.y;
    #pragma unroll
    for (int j = 0; j < 32; j += 8)
        t[ty + j][tx] = in[(size_t)(by + ty + j) * C + bx + tx];
    __syncthreads();
    #pragma unroll
    for (int j = 0; j < 32; j += 8)
        out[(size_t)(bx + ty + j) * R + by + tx] = __float2bfloat16(t[tx][ty + j]);
}

// ---------------------------------------------------------------------------
// Prep B: x fp32->bf16 (blocks 0..n4/256-1) + mask dtype probe (last block)
// ---------------------------------------------------------------------------
__global__ void prep_conv_probe(const float* __restrict__ x,
                                __nv_bfloat16* __restrict__ xh, int n4,
                                const uint4* __restrict__ m) {
    int nconv = (n4 + 255) / 256;
    if ((int)blockIdx.x < nconv) {
        int i = blockIdx.x * 256 + threadIdx.x;
        if (i < n4) {
            float4 v = *(const float4*)(x + (size_t)i * 4);
            __nv_bfloat162 a = __floats2bfloat162_rn(v.x, v.y);
            __nv_bfloat162 b = __floats2bfloat162_rn(v.z, v.w);
            *(uint2*)(xh + (size_t)i * 4) = make_uint2(*(uint32_t*)&a, *(uint32_t*)&b);
        }
        return;
    }
    // probe: 256 threads scan 4KB
    __shared__ int s_flags;
    if (threadIdx.x == 0) s_flags = 0;
    __syncthreads();
    uint4 v = m[threadIdx.x];
    unsigned int ws[4] = {v.x, v.y, v.z, v.w};
    int f = 0;
    #pragma unroll
    for (int i = 0; i < 4; i++) {
        unsigned int w = ws[i];
        if (w > 1u)                      f |= 1;
        if ((w & 0xFEFEFEFEu) != 0u)     f |= 2;
        if (w != 0u && w != 0x3F800000u) f |= 4;
    }
    if (f) atomicOr(&s_flags, f);
    __syncthreads();
    if (threadIdx.x == 0) {
        int fl = s_flags, mode;
        if      (!(fl & 1)) mode = 0;
        else if (!(fl & 2)) mode = 1;
        else if (!(fl & 4)) mode = 2;
        else                mode = 1;
        g_mask_mode = mode;
    }
}

// ---------------------------------------------------------------------------
// bf16 TC GEMM: C[M,N] = A[M,K] @ Bt[N,K]^T + bias (+resid)
// 128x128x32 CTA tile, 8 warps of 32x64, 3-stage cp.async, 1 sync/iter.
// ---------------------------------------------------------------------------
#define GTILE (128 * 40)

template<int OUT_BF16>
__global__ __launch_bounds__(256) void gemm_bf16(
    const __nv_bfloat16* __restrict__ A, const __nv_bfloat16* __restrict__ Bt,
    const float* __restrict__ bias, const float* __restrict__ resid,
    void* __restrict__ C, int M, int N, int K)
{
    extern __shared__ __nv_bfloat16 smg[];
    __nv_bfloat16* Asm = smg;                 // [3][128*40]
    __nv_bfloat16* Bsm = smg + 3 * GTILE;     // [3][128*40]

    const int tid = threadIdx.x;
    const int wid = tid >> 5, lane = tid & 31;
    const int g = lane >> 2, tg = lane & 3;
    const int wm = wid >> 1, wn = wid & 1;
    const int row0 = blockIdx.y * 128, col0 = blockIdx.x * 128;
    const int m0 = wm * 32, n0 = wn * 64;

    const int la_row = lane & 15,  la_k = (lane >> 4) * 8;
    const int lb_row = (lane & 7) + (lane >> 4) * 8;
    const int lb_k   = ((lane >> 3) & 1) * 8;

    float acc[2][8][4];
    #pragma unroll
    for (int i = 0; i < 2; i++)
        #pragma unroll
        for (int j = 0; j < 8; j++)
            #pragma unroll
            for (int c = 0; c < 4; c++) acc[i][j][c] = 0.f;

    auto issue = [&](int stage, int kt) {
        #pragma unroll
        for (int i = 0; i < 2; i++) {
            int idx = tid + i * 256;
            int r = idx >> 2, sg = (idx & 3) * 8;
            CP_ASYNC16(sptr(&Asm[stage * GTILE + r * 40 + sg]),
                       A + (size_t)(row0 + r) * K + kt + sg);
            CP_ASYNC16(sptr(&Bsm[stage * GTILE + r * 40 + sg]),
                       Bt + (size_t)(col0 + r) * K + kt + sg);
        }
    };

    const int NT = K / 32;
    issue(0, 0);  CP_COMMIT();
    issue(1, 32); CP_COMMIT();

    for (int i = 0; i < NT; i++) {
        CP_WAIT1();
        __syncthreads();
        if (i + 2 < NT) issue((i + 2) % 3, (i + 2) * 32);
        CP_COMMIT();

        const __nv_bfloat16* as = &Asm[(i % 3) * GTILE];
        const __nv_bfloat16* bs = &Bsm[(i % 3) * GTILE];
        #pragma unroll
        for (int ks = 0; ks < 2; ks++) {
            int k16 = ks * 16;
            uint32_t a[2][4];
            #pragma unroll
            for (int mt = 0; mt < 2; mt++)
                ldsm_x4(a[mt][0], a[mt][1], a[mt][2], a[mt][3],
                        sptr(&as[(m0 + mt * 16 + la_row) * 40 + k16 + la_k]));
            #pragma unroll
            for (int p = 0; p < 4; p++) {
                uint32_t b0, b1, b2, b3;
                ldsm_x4(b0, b1, b2, b3,
                        sptr(&bs[(n0 + p * 16 + lb_row) * 40 + k16 + lb_k]));
                mma16816(acc[0][2 * p],     a[0], b0, b1);
                mma16816(acc[1][2 * p],     a[1], b0, b1);
                mma16816(acc[0][2 * p + 1], a[0], b2, b3);
                mma16816(acc[1][2 * p + 1], a[1], b2, b3);
            }
        }
    }

    #pragma unroll
    for (int mt = 0; mt < 2; mt++) {
        #pragma unroll
        for (int half = 0; half < 2; half++) {
            int r = row0 + m0 + mt * 16 + g + half * 8;
            #pragma unroll
            for (int nt = 0; nt < 8; nt++) {
                int c = col0 + n0 + nt * 8 + tg * 2;
                float v0 = acc[mt][nt][half * 2 + 0] + bias[c];
                float v1 = acc[mt][nt][half * 2 + 1] + bias[c + 1];
                if (OUT_BF16) {
                    *(__nv_bfloat162*)((__nv_bfloat16*)C + (size_t)r * N + c) =
                        __floats2bfloat162_rn(v0, v1);
                } else {
                    float2 rv = *(const float2*)&resid[(size_t)r * N + c];
                    *(float2*)((float*)C + (size_t)r * N + c) =
                        make_float2(v0 + rv.x, v1 + rv.y);
                }
            }
        }
    }
}

// ---------------------------------------------------------------------------
// FA2 attention: CTA = 128 q-rows of one (b,h); 8 warps x m16 x n64.
// 3-stage cp.async K/V (stride 88 = conflict-free ldsm), 1 sync/iter.
// ---------------------------------------------------------------------------
#define KVSTRIDE 88
#define KVTILE (64 * KVSTRIDE)

__global__ __launch_bounds__(256) void attn_kernel(
    const void* __restrict__ mask, __nv_bfloat16* __restrict__ ctx)
{
    extern __shared__ __nv_bfloat16 sma[];
    __nv_bfloat16* Ksm = sma;                  // [3][64*88]
    __nv_bfloat16* Vsm = sma + 3 * KVTILE;     // [3][64*88]

    const int tid = threadIdx.x;
    const int wid = tid >> 5, lane = tid & 31;
    const int g = lane >> 2, tg = lane & 3;
    const int q0 = blockIdx.x * 128;
    const int h = blockIdx.y, b = blockIdx.z;
    const int mmode = g_mask_mode;
    const int qrow = q0 + wid * 16 + g;
    const size_t qbase = (size_t)(b * SS + qrow) * QKVC + h * 192;

    const int lk_row = (lane & 7) + (lane >> 4) * 8;
    const int lk_k   = ((lane >> 3) & 1) * 8;
    const int lv_row = (lane & 7) + ((lane >> 3) & 1) * 8;
    const int lv_c   = (lane >> 4) * 8;

    auto issueKV = [&](int stage, int kt) {
        #pragma unroll
        for (int i = 0; i < 2; i++) {
            int idx = tid + i * 256;
            int tok = idx >> 3, sg = (idx & 7) * 8;
            const __nv_bfloat16* src =
                g_qkvh + (size_t)(b * SS + kt + tok) * QKVC + h * 192;
            CP_ASYNC16(sptr(&Ksm[stage * KVTILE + tok * KVSTRIDE + sg]), src + 64 + sg);
            CP_ASYNC16(sptr(&Vsm[stage * KVTILE + tok * KVSTRIDE + sg]), src + 128 + sg);
        }
    };

    issueKV(0, 0);  CP_COMMIT();
    issueKV(1, 64); CP_COMMIT();

    // Q fragments (prescaled by 0.125, exact in bf16)
    uint32_t qa[4][4];
    const __nv_bfloat162 sc = __floats2bfloat162_rn(0.125f, 0.125f);
    #pragma unroll
    for (int t = 0; t < 4; t++) {
        int d = t * 16 + tg * 2;
        __nv_bfloat162 v;
        v = __hmul2(*(const __nv_bfloat162*)&g_qkvh[qbase + d], sc);
        qa[t][0] = *reinterpret_cast<uint32_t*>(&v);
        v = __hmul2(*(const __nv_bfloat162*)&g_qkvh[qbase + (size_t)8 * QKVC + d], sc);
        qa[t][1] = *reinterpret_cast<uint32_t*>(&v);
        v = __hmul2(*(const __nv_bfloat162*)&g_qkvh[qbase + d + 8], sc);
        qa[t][2] = *reinterpret_cast<uint32_t*>(&v);
        v = __hmul2(*(const __nv_bfloat162*)&g_qkvh[qbase + (size_t)8 * QKVC + d + 8], sc);
        qa[t][3] = *reinterpret_cast<uint32_t*>(&v);
    }

    float O[8][4];
    #pragma unroll
    for (int nt = 0; nt < 8; nt++)
        #pragma unroll
        for (int c = 0; c < 4; c++) O[nt][c] = 0.f;
    float mstat[2] = {-1e30f, -1e30f};
    float lstat[2] = {0.f, 0.f};

    for (int it = 0; it < SS / 64; it++) {
        const int kt = it * 64;
        CP_WAIT1();
        __syncthreads();
        if (kt + 128 < SS) issueKV((it + 2) % 3, kt + 128);
        CP_COMMIT();

        const __nv_bfloat16* ks = &Ksm[(it % 3) * KVTILE];
        const __nv_bfloat16* vs = &Vsm[(it % 3) * KVTILE];

        // Prefetch mask into packed regs (LDG hidden under S MMAs)
        uint32_t mpk[2][8];
        #pragma unroll
        for (int r = 0; r < 2; r++) {
            size_t mrow = ((size_t)(b * SS + qrow + r * 8) * NHEAD + h) * SS + kt;
            #pragma unroll
            for (int nt = 0; nt < 8; nt++) {
                int kc = nt * 8 + tg * 2;
                if (mmode == 0) {
                    int2 v = *(const int2*)((const int*)mask + mrow + kc);
                    mpk[r][nt] = (v.x ? 1u : 0u) | (v.y ? 2u : 0u);
                } else if (mmode == 1) {
                    const unsigned char* mp = (const unsigned char*)mask + mrow + kc;
                    mpk[r][nt] = (mp[0] ? 1u : 0u) | (mp[1] ? 2u : 0u);
                } else {
                    float2 v = *(const float2*)((const float*)mask + mrow + kc);
                    mpk[r][nt] = (v.x != 0.f ? 1u : 0u) | (v.y != 0.f ? 2u : 0u);
                }
            }
        }

        // S = (Q/8) @ K^T
        float s[8][4];
        #pragma unroll
        for (int nt = 0; nt < 8; nt++)
            #pragma unroll
            for (int c = 0; c < 4; c++) s[nt][c] = 0.f;
        #pragma unroll
        for (int t = 0; t < 4; t++) {
            #pragma unroll
            for (int p = 0; p < 4; p++) {
                uint32_t b0, b1, b2, b3;
                ldsm_x4(b0, b1, b2, b3,
                        sptr(&ks[(p * 16 + lk_row) * KVSTRIDE + t * 16 + lk_k]));
                mma16816(s[2 * p],     qa[t], b0, b1);
                mma16816(s[2 * p + 1], qa[t], b2, b3);
            }
        }

        // apply mask
        #pragma unroll
        for (int r = 0; r < 2; r++)
            #pragma unroll
            for (int nt = 0; nt < 8; nt++) {
                if (!(mpk[r][nt] & 1u)) s[nt][r * 2 + 0] = NEG_INF;
                if (!(mpk[r][nt] & 2u)) s[nt][r * 2 + 1] = NEG_INF;
            }

        // online softmax (branch-free; running max clamped at -1e30)
        float alpha[2];
        #pragma unroll
        for (int r = 0; r < 2; r++) {
            float mloc = NEG_INF;
            #pragma unroll
            for (int nt = 0; nt < 8; nt++)
                mloc = fmaxf(mloc, fmaxf(s[nt][r * 2], s[nt][r * 2 + 1]));
            mloc = fmaxf(mloc, __shfl_xor_sync(0xffffffffu, mloc, 1));
            mloc = fmaxf(mloc, __shfl_xor_sync(0xffffffffu, mloc, 2));
            float mnew = fmaxf(mstat[r], mloc);
            float a = __expf(mstat[r] - mnew);
            float sum = 0.f;
            #pragma unroll
            for (int nt = 0; nt < 8; nt++) {
                #pragma unroll
                for (int j = 0; j < 2; j++) {
                    float p = __expf(s[nt][r * 2 + j] - mnew);  // exp(-inf)=0
                    s[nt][r * 2 + j] = p;
                    sum += p;
                }
            }
            sum += __shfl_xor_sync(0xffffffffu, sum, 1);
            sum += __shfl_xor_sync(0xffffffffu, sum, 2);
            lstat[r] = lstat[r] * a + sum;
            mstat[r] = mnew;
            alpha[r] = a;
        }
        #pragma unroll
        for (int nt = 0; nt < 8; nt++) {
            O[nt][0] *= alpha[0]; O[nt][1] *= alpha[0];
            O[nt][2] *= alpha[1]; O[nt][3] *= alpha[1];
        }

        // O += P @ V
        #pragma unroll
        for (int t = 0; t < 4; t++) {
            uint32_t pa[4];
            pa[0] = pack_bf16(s[2 * t][0],     s[2 * t][1]);
            pa[1] = pack_bf16(s[2 * t][2],     s[2 * t][3]);
            pa[2] = pack_bf16(s[2 * t + 1][0], s[2 * t + 1][1]);
            pa[3] = pack_bf16(s[2 * t + 1][2], s[2 * t + 1][3]);
            #pragma unroll
            for (int p = 0; p < 4; p++) {
                uint32_t b0, b1, b2, b3;
                ldsm_x4_t(b0, b1, b2, b3,
                          sptr(&vs[(16 * t + lv_row) * KVSTRIDE + p * 16 + lv_c]));
                mma16816(O[2 * p],     pa, b0, b1);
                mma16816(O[2 * p + 1], pa, b2, b3);
            }
        }
    }

    // normalize + write ctx (bf16)
    float linv0 = (lstat[0] > 0.f) ? (1.f / lstat[0]) : 0.f;
    float linv1 = (lstat[1] > 0.f) ? (1.f / lstat[1]) : 0.f;
    size_t obase0 = (size_t)(b * SS + qrow) * NHID + h * 64 + tg * 2;
    size_t obase1 = obase0 + (size_t)8 * NHID;
    #pragma unroll
    for (int nt = 0; nt < 8; nt++) {
        *(uint32_t*)&ctx[obase0 + nt * 8] = pack_bf16(O[nt][0] * linv0, O[nt][1] * linv0);
        *(uint32_t*)&ctx[obase1 + nt * 8] = pack_bf16(O[nt][2] * linv1, O[nt][3] * linv1);
    }
}

// ---------------------------------------------------------------------------
extern "C" void kernel_launch(void* const* d_in, const int* in_sizes, int n_in,
                              void* d_out, int out_size)
{
    const float* x     = (const float*)d_in[0];
    const void*  mask  = d_in[1];
    const float* W_qkv = (const float*)d_in[2];
    const float* b_qkv = (const float*)d_in[3];
    const float* W_out = (const float*)d_in[4];
    const float* b_out = (const float*)d_in[5];
    float*       out   = (float*)d_out;

    __nv_bfloat16 *xh, *qkvh, *ctxh, *wqkvt, *woutt;
    cudaGetSymbolAddress((void**)&xh,    g_xh);
    cudaGetSymbolAddress((void**)&qkvh,  g_qkvh);
    cudaGetSymbolAddress((void**)&ctxh,  g_ctxh);
    cudaGetSymbolAddress((void**)&wqkvt, g_wqkvt);
    cudaGetSymbolAddress((void**)&woutt, g_woutt);

    const int smem_gemm = 6 * GTILE * (int)sizeof(__nv_bfloat16);    // 61440
    const int smem_attn = 6 * KVTILE * (int)sizeof(__nv_bfloat16);   // 67584
    cudaFuncSetAttribute(gemm_bf16<1>, cudaFuncAttributeMaxDynamicSharedMemorySize, smem_gemm);
    cudaFuncSetAttribute(gemm_bf16<0>, cudaFuncAttributeMaxDynamicSharedMemorySize, smem_gemm);
    cudaFuncSetAttribute(attn_kernel,  cudaFuncAttributeMaxDynamicSharedMemorySize, smem_attn);

    // 0) Prep: fused weight transposes; x->bf16 + mask probe
    prep_transpose<<<dim3(QKVC / 32, NHID / 32, 2), dim3(32, 8)>>>(W_qkv, W_out, wqkvt, woutt);
    const int n4 = ROWS * NHID / 4;
    prep_conv_probe<<<(n4 + 255) / 256 + 1, 256>>>(x, xh, n4, (const uint4*)mask);

    // 1) QKV projection (bf16 in, bf16 out)
    gemm_bf16<1><<<dim3(QKVC / 128, ROWS / 128), 256, smem_gemm>>>(
        xh, wqkvt, b_qkv, nullptr, qkvh, ROWS, QKVC, NHID);

    // 2) Masked flash attention (bf16 tensor cores)
    attn_kernel<<<dim3(SS / 128, NHEAD, BB), 256, smem_attn>>>(mask, ctxh);

    // 3) Output projection + bias + residual (bf16 in, fp32 out)
    gemm_bf16<0><<<dim3(NHID / 128, ROWS / 128), 256, smem_gemm>>>(
        ctxh, woutt, b_out, x, out, ROWS, NHID, NHID);
}